// round 17
// baseline (speedup 1.0000x reference)
#include <cuda_runtime.h>
#include <cuda_fp16.h>
#include <cstdint>

// GRU encoder B=512 T=128 E=H=512 L=2 — R17: fully fused superstep kernel.
// One kernel per superstep: CTAs own gate-aligned weight columns {j,512+j,1024+j}
// so GRU gate math runs in the GEMM epilogue (no scratch, no gate kernel).
// L0 CTAs: h0(t) = GRU(P[tok], h0(t-1)@Wh0^T, h0(t-1));  128 CTAs, tile 64x(3x32).
// L1 CTAs: h1(t-1) via 2 passes (gi1 then gh1 accumulated, i_n saved);
//          256 CTAs, tile 64x(3x16). Hidden-state fp16 operands double-buffered
//          by step parity (L0 writes h0(t) while L1 reads h0(t-1) in the same grid).

namespace {

constexpr int B_ = 512, T_ = 128, H_ = 512, L_ = 2;
constexpr int NG = 1536;
constexpr size_t BH  = (size_t)B_ * H_;
constexpr size_t WSZ = (size_t)NG * 512;
constexpr int THR = 128;                    // 4 warps
constexpr int M = 64;                       // batch rows per CTA
constexpr int KC = 64;
constexpr int A_B = M * 128;                // 8192 B (64 rows x 64 fp16, SW128)
constexpr int STAGE = A_B + 96 * 128;       // 20480 (B region sized for L0's 96 rows)
constexpr int SMEM_ALLOC = 3 * STAGE;       // 61440 -> 3 CTAs/SM

__device__ __align__(256) float g_P[128 * NG];     // emb@Wi0^T + b_ih0 + b_hh0(r,z)
__device__ __align__(256) __half g_W[3 * WSZ];     // Wh0 | Wi1 | Wh1 (fp16)
__device__ __align__(256) __half g_Ah0[2 * BH];    // h0 fp16, parity buffers
__device__ __align__(256) __half g_Ah1[2 * BH];    // h1 fp16, parity buffers

__device__ __forceinline__ uint32_t s2u(const void* p) {
    uint32_t a;
    asm("{ .reg .u64 t; cvta.to.shared.u64 t, %1; cvt.u32.u64 %0, t; }" : "=r"(a) : "l"(p));
    return a;
}
__device__ __forceinline__ uint32_t sw128(uint32_t b) { return b ^ ((b >> 3) & 0x70); }
__device__ __forceinline__ void cp16(uint32_t dst, const void* src) {
    asm volatile("cp.async.cg.shared.global [%0], [%1], 16;" :: "r"(dst), "l"(src));
}
__device__ __forceinline__ void ldsm4(uint32_t* r, uint32_t addr) {
    asm volatile("ldmatrix.sync.aligned.m8n8.x4.shared.b16 {%0,%1,%2,%3}, [%4];"
                 : "=r"(r[0]), "=r"(r[1]), "=r"(r[2]), "=r"(r[3]) : "r"(addr));
}
__device__ __forceinline__ void mma16816(float* c, const uint32_t* a, const uint32_t* b) {
    asm volatile(
        "mma.sync.aligned.m16n8k16.row.col.f32.f16.f16.f32 "
        "{%0,%1,%2,%3}, {%4,%5,%6,%7}, {%8,%9}, {%0,%1,%2,%3};"
        : "+f"(c[0]), "+f"(c[1]), "+f"(c[2]), "+f"(c[3])
        : "r"(a[0]), "r"(a[1]), "r"(a[2]), "r"(a[3]), "r"(b[0]), "r"(b[1]));
}
__device__ __forceinline__ void pdl_wait() {
    asm volatile("griddepcontrol.wait;" ::: "memory");
}
__device__ __forceinline__ void pdl_trigger() {
    asm volatile("griddepcontrol.launch_dependents;" ::: "memory");
}
__device__ __forceinline__ float sigf(float x) { return 1.0f / (1.0f + expf(-x)); }

// ---------------- fused tile: GEMM(s) + GRU gate epilogue ----------------
template <int LAYER>
__device__ __forceinline__ void run_tile(
        int m0, int n0h, int s, int wp,
        const __half* a0p, const __half* a1p,
        const __half* b0p, const __half* b1p,
        float* out, const int* input, const float* h0init,
        const float* b_ih, const float* b_hh, int write_final, char* smraw) {
    constexpr int NH   = (LAYER == 0) ? 32 : 16;  // hidden units per CTA
    constexpr int NB   = 3 * NH;                  // B rows (3 gates)
    constexpr int NI   = NB / 8;                  // n8 fragments
    constexpr int NIg  = NH / 8;                  // fragments per gate
    constexpr int NGR  = NB / 16;                 // ldsm 16-row groups
    constexpr int BI   = NB * 8 / THR;            // B cp16 per thread
    constexpr int NITER = (LAYER == 0) ? 8 : 16;  // stages (L1: 2 passes x 8)

    const int tid = threadIdx.x, wid = tid >> 5, lane = tid & 31;
    const uint32_t smb = s2u(smraw);

    auto load_B = [&](int sIdx) {
        const int buf = sIdx % 3;
        const int k0 = (sIdx & 7) * KC;
        const __half* Bs = (LAYER == 0) ? b0p : ((sIdx >> 3) ? b1p : b0p);
        const uint32_t st = smb + buf * STAGE + A_B;
        #pragma unroll
        for (int i = 0; i < BI; i++) {
            int c = tid + i * THR;
            int p = c >> 3, col = c & 7;
            int g = p / NH, jj = p % NH;
            cp16(st + sw128((uint32_t)(p * 128 + col * 16)),
                 Bs + (size_t)(g * 512 + n0h + jj) * 512 + k0 + col * 8);
        }
    };
    auto load_A = [&](int sIdx) {
        const int buf = sIdx % 3;
        const int k0 = (sIdx & 7) * KC;
        const __half* As = (LAYER == 0) ? a0p : ((sIdx >> 3) ? a1p : a0p);
        const uint32_t st = smb + buf * STAGE;
        #pragma unroll
        for (int i = 0; i < 4; i++) {
            int c = tid + i * THR;
            int row = c >> 3, col = c & 7;
            cp16(st + sw128((uint32_t)(row * 128 + col * 16)),
                 As + (size_t)(m0 + row) * 512 + k0 + col * 8);
        }
    };

    // pre-wait: B only (g_W is constant) -> overlaps predecessor grid
    load_B(0); asm volatile("cp.async.commit_group;");
    load_B(1); asm volatile("cp.async.commit_group;");
    load_B(2); asm volatile("cp.async.commit_group;");
    pdl_wait();
    load_A(0); asm volatile("cp.async.commit_group;");
    load_A(1); asm volatile("cp.async.commit_group;");
    load_A(2); asm volatile("cp.async.commit_group;");

    const int aRow  = wid * 16 + (lane & 15);
    const int aKsel = ((lane >> 4) & 1) * 16;
    const int bRow  = ((lane >> 4) & 1) * 8 + (lane & 7);
    const int bKsel = ((lane >> 3) & 1) * 16;

    float acc[NI][4];
    #pragma unroll
    for (int ni = 0; ni < NI; ni++)
        #pragma unroll
        for (int q = 0; q < 4; q++) acc[ni][q] = 0.0f;
    float sv[NIg][4];   // L1: saved i_n fragments

    for (int j = 0; j < NITER; j++) {
        asm volatile("cp.async.wait_group 2;");   // uniform (commit every iter)
        __syncthreads();
        const uint32_t stA = smb + (j % 3) * STAGE;
        const uint32_t stB = stA + A_B;
        #pragma unroll
        for (int ks = 0; ks < 4; ks++) {
            uint32_t a[4], b[NGR][4];
            ldsm4(a, stA + sw128((uint32_t)(aRow * 128 + ks * 32 + aKsel)));
            #pragma unroll
            for (int g = 0; g < NGR; g++)
                ldsm4(b[g], stB + sw128((uint32_t)((bRow + g * 16) * 128 + ks * 32 + bKsel)));
            #pragma unroll
            for (int ni = 0; ni < NI; ni++)
                mma16816(acc[ni], a, &b[ni >> 1][(ni & 1) * 2]);
        }
        if (LAYER == 1 && j == 7) {               // end of pass 0: save i_n
            #pragma unroll
            for (int k = 0; k < NIg; k++)
                #pragma unroll
                for (int q = 0; q < 4; q++) sv[k][q] = acc[2 * NIg + k][q];
        }
        __syncthreads();                          // buf j%3 fully consumed
        if (j + 3 < NITER) { load_A(j + 3); load_B(j + 3); }
        asm volatile("cp.async.commit_group;");   // one group per iter (may be empty)
        if (j + 4 == NITER) pdl_trigger();        // all gmem A reads issued
    }

    // ---------------- fused gate epilogue ----------------
    const int row0 = m0 + wid * 16 + (lane >> 2);
    const int lane4 = (lane & 3) * 2;
    const float* hp_base = (s == 0) ? (h0init + (size_t)LAYER * BH)
                                    : (out + (size_t)((s - 1) * L_ + LAYER) * BH);
    float* out_base = out + (size_t)(s * L_ + LAYER) * BH;
    float* fin_base = out + (size_t)T_ * L_ * BH + (size_t)LAYER * BH;
    __half* ah_base = (LAYER == 0 ? g_Ah0 : g_Ah1) + (size_t)wp * BH;

    #pragma unroll
    for (int nr = 0; nr < NIg; nr++) {
        const int j = n0h + nr * 8 + lane4;
        float2 bhn = *(const float2*)(b_hh + (size_t)LAYER * NG + 1024 + j);
        float2 crz_r, crz_z, bin;
        if (LAYER == 1) {                       // L0 biases are folded into P
            float2 a1 = *(const float2*)(b_ih + NG + j);
            float2 a2 = *(const float2*)(b_hh + NG + j);
            crz_r = make_float2(a1.x + a2.x, a1.y + a2.y);
            a1 = *(const float2*)(b_ih + NG + 512 + j);
            a2 = *(const float2*)(b_hh + NG + 512 + j);
            crz_z = make_float2(a1.x + a2.x, a1.y + a2.y);
            bin = *(const float2*)(b_ih + NG + 1024 + j);
        }
        #pragma unroll
        for (int rq = 0; rq < 2; rq++) {
            const int row = row0 + rq * 8;
            float2 hp = *(const float2*)(hp_base + (size_t)row * H_ + j);
            float2 Pr, Pz, Pn;
            if (LAYER == 0) {
                const float* P = g_P + (size_t)input[row * T_ + s] * NG + j;
                Pr = *(const float2*)(P);
                Pz = *(const float2*)(P + 512);
                Pn = *(const float2*)(P + 1024);
            }
            float h2[2];
            #pragma unroll
            for (int q2 = 0; q2 < 2; q2++) {
                const int q = rq * 2 + q2;
                float r, z, n;
                if (LAYER == 0) {
                    r = sigf((&Pr.x)[q2] + acc[nr][q]);
                    z = sigf((&Pz.x)[q2] + acc[nr + NIg][q]);
                    n = tanhf((&Pn.x)[q2] +
                              r * (acc[nr + 2 * NIg][q] + (&bhn.x)[q2]));
                } else {
                    float i_n = sv[nr][q];
                    float h_n = acc[nr + 2 * NIg][q] - i_n;
                    r = sigf(acc[nr][q] + (&crz_r.x)[q2]);
                    z = sigf(acc[nr + NIg][q] + (&crz_z.x)[q2]);
                    n = tanhf(i_n + (&bin.x)[q2] + r * (h_n + (&bhn.x)[q2]));
                }
                h2[q2] = (1.0f - z) * n + z * (&hp.x)[q2];
            }
            *(float2*)(out_base + (size_t)row * H_ + j) = make_float2(h2[0], h2[1]);
            *(__half2*)(ah_base + (size_t)row * H_ + j) = __floats2half2_rn(h2[0], h2[1]);
            if (write_final && s == T_ - 1)
                *(float2*)(fin_base + (size_t)row * H_ + j) = make_float2(h2[0], h2[1]);
        }
    }
}

__global__ void __launch_bounds__(THR, 3) step_fused(
        float* __restrict__ out, const int* __restrict__ input,
        const float* __restrict__ h0init,
        const float* __restrict__ b_ih, const float* __restrict__ b_hh,
        int t, int write_final) {
    extern __shared__ char smraw[];
    const int cid = blockIdx.x;
    const int rp = (t + 1) & 1;   // read parity (= (t-1)&1)
    const int wp = t & 1;         // write parity
    if (cid < 128) {              // layer 0, step s = t
        if (t >= T_) return;
        run_tile<0>((cid >> 4) * M, (cid & 15) * 32, t, wp,
                    g_Ah0 + (size_t)rp * BH, nullptr, g_W, nullptr,
                    out, input, h0init, b_ih, b_hh, write_final, smraw);
    } else {                      // layer 1, step s = t-1
        if (t < 1) return;
        const int id = cid - 128;
        run_tile<1>((id >> 5) * M, (id & 31) * 16, t - 1, wp,
                    g_Ah0 + (size_t)rp * BH, g_Ah1 + (size_t)rp * BH,
                    g_W + WSZ, g_W + 2 * WSZ,
                    out, input, h0init, b_ih, b_hh, write_final, smraw);
    }
}

// ============================ prep ============================
// P[v][n] = emb[v]@Wi0[n] + b_ih0[n] + (n<1024 ? b_hh0[n] : 0)
__global__ void __launch_bounds__(256) prep_P(const float* __restrict__ emb,
                                              const float* __restrict__ w_ih,
                                              const float* __restrict__ b_ih,
                                              const float* __restrict__ b_hh) {
    const int n0 = blockIdx.x * 128;
    const int v0 = blockIdx.y * 16;
    const int tid = threadIdx.x;
    const int nq = tid & 31;
    const int vq = tid >> 5;

    __shared__ float ws[32][132];
    __shared__ float es[32][17];

    float acc[2][4];
    #pragma unroll
    for (int i = 0; i < 2; i++)
        #pragma unroll
        for (int j = 0; j < 4; j++) acc[i][j] = 0.0f;

    for (int k0 = 0; k0 < 512; k0 += 32) {
        __syncthreads();
        {
            int k = tid & 31, v = tid >> 5;
            es[k][v]     = emb[(size_t)(v0 + v) * 512 + k0 + k];
            es[k][v + 8] = emb[(size_t)(v0 + v + 8) * 512 + k0 + k];
        }
        #pragma unroll
        for (int p = 0; p < 16; p++) {
            int idx = tid + p * 256, k = idx & 31, n = idx >> 5;
            ws[k][n] = w_ih[(size_t)(n0 + n) * 512 + k0 + k];
        }
        __syncthreads();
        #pragma unroll 8
        for (int kk = 0; kk < 32; kk++) {
            float a0 = es[kk][vq], a1 = es[kk][vq + 8];
            float4 w = *(const float4*)&ws[kk][nq * 4];
            #pragma unroll
            for (int j = 0; j < 4; j++) {
                acc[0][j] = fmaf(a0, (&w.x)[j], acc[0][j]);
                acc[1][j] = fmaf(a1, (&w.x)[j], acc[1][j]);
            }
        }
    }

    #pragma unroll
    for (int j = 0; j < 4; j++) {
        int n = n0 + nq * 4 + j;
        float bias = b_ih[n] + (n < 1024 ? b_hh[n] : 0.0f);
        acc[0][j] += bias;
        acc[1][j] += bias;
    }
    *(float4*)&g_P[(size_t)(v0 + vq) * NG + n0 + nq * 4] =
        make_float4(acc[0][0], acc[0][1], acc[0][2], acc[0][3]);
    *(float4*)&g_P[(size_t)(v0 + vq + 8) * NG + n0 + nq * 4] =
        make_float4(acc[1][0], acc[1][1], acc[1][2], acc[1][3]);
}

__global__ void __launch_bounds__(256) prep_W(const float* __restrict__ w_ih,
                                              const float* __restrict__ w_hh) {
    size_t e4 = ((size_t)blockIdx.x * 256 + threadIdx.x) * 4;
    size_t job = e4 / WSZ, off = e4 % WSZ;
    const float* src = (job == 0) ? (w_hh + off)
                     : (job == 1) ? (w_ih + WSZ + off) : (w_hh + WSZ + off);
    float4 v = *(const float4*)src;
    union { __half b[4]; uint2 u; } hh;
    hh.b[0] = __float2half_rn(v.x); hh.b[1] = __float2half_rn(v.y);
    hh.b[2] = __float2half_rn(v.z); hh.b[3] = __float2half_rn(v.w);
    *(uint2*)(g_W + e4) = hh.u;
}

// init: g_Ah0 parity1 <- h0init[layer0]; g_Ah1 parity0 <- h0init[layer1]
__global__ void __launch_bounds__(256) prep_A(const float* __restrict__ h0) {
    size_t e4 = ((size_t)blockIdx.x * 256 + threadIdx.x) * 4;   // over 2*BH
    float4 v = *(const float4*)(h0 + e4);
    union { __half b[4]; uint2 u; } hh;
    hh.b[0] = __float2half_rn(v.x); hh.b[1] = __float2half_rn(v.y);
    hh.b[2] = __float2half_rn(v.z); hh.b[3] = __float2half_rn(v.w);
    if (e4 < BH) *(uint2*)(g_Ah0 + BH + e4) = hh.u;          // layer0 -> parity 1
    else         *(uint2*)(g_Ah1 + (e4 - BH)) = hh.u;        // layer1 -> parity 0
}

} // namespace

extern "C" void kernel_launch(void* const* d_in, const int* in_sizes, int n_in,
                              void* d_out, int out_size) {
    const int*   input = (const int*)  d_in[0];
    const float* h0    = (const float*)d_in[1];
    const float* emb   = (const float*)d_in[2];
    const float* w_ih  = (const float*)d_in[3];
    const float* w_hh  = (const float*)d_in[4];
    const float* b_ih  = (const float*)d_in[5];
    const float* b_hh  = (const float*)d_in[6];
    float* out = (float*)d_out;

    const long long states_elems = (long long)T_ * L_ * B_ * H_;
    int write_final =
        ((long long)out_size >= states_elems + (long long)L_ * B_ * H_) ? 1 : 0;

    cudaFuncSetAttribute(step_fused, cudaFuncAttributeMaxDynamicSharedMemorySize,
                         SMEM_ALLOC);

    prep_W<<<(int)(3 * WSZ / 4 / 256), 256>>>(w_ih, w_hh);
    prep_A<<<(int)(2 * BH / 4 / 256), 256>>>(h0);
    prep_P<<<dim3(12, 8), 256>>>(emb, w_ih, b_ih, b_hh);

    cudaLaunchAttribute attrs[1];
    attrs[0].id = cudaLaunchAttributeProgrammaticStreamSerialization;
    attrs[0].val.programmaticStreamSerializationAllowed = 1;

    for (int t = 0; t <= T_; t++) {
        cudaLaunchConfig_t cfg = {};
        cfg.gridDim = dim3(384, 1, 1);   // 128 L0 CTAs + 256 L1 CTAs
        cfg.blockDim = dim3(THR);
        cfg.dynamicSmemBytes = SMEM_ALLOC;
        cfg.stream = 0;
        cfg.attrs = attrs;
        cfg.numAttrs = 1;
        void* args[] = {&out, &input, &h0, &b_ih, &b_hh, &t, &write_final};
        cudaLaunchKernelExC(&cfg, (const void*)step_fused, args);
    }
}